// round 16
// baseline (speedup 1.0000x reference)
#include <cuda_runtime.h>
#include <cuda_fp16.h>
#include <math.h>
#include <stdint.h>

#define BQ   16384
#define DIN  256
#define DHID 512
#define DOUT 256
#define NE   8
#define BKC  64
#define NPERS 296   // persistent CTAs = 2 per SM x 148

// ---------------- scratch (static device globals; no allocations) ----------
__device__ int   g_count[NE];
__device__ int   g_list[NE * BQ];                 // pair id (2t+k) per (expert, slot)
__device__ float g_pw[2 * BQ];
__device__ __align__(16) __half g_xh[(size_t)BQ * DIN];       // fp16 x
__device__ __align__(16) __half g_W1h[NE * DIN * DHID];       // [e][k][n] fp16
__device__ __align__(16) __half g_W2h[NE * DHID * DOUT];      // [e][k][n] fp16
__device__ __align__(16) __half g_Hh[(size_t)2 * BQ * DHID];  // fp16 hidden (slot space)

// ---------------- helpers ----------------------------------------------------
__device__ __forceinline__ uint32_t smem_u32(const void* p) {
    return (uint32_t)__cvta_generic_to_shared(p);
}
__device__ __forceinline__ void ldmx4(uint32_t* r, uint32_t a) {
    asm volatile("ldmatrix.sync.aligned.m8n8.x4.shared.b16 {%0,%1,%2,%3}, [%4];"
                 : "=r"(r[0]), "=r"(r[1]), "=r"(r[2]), "=r"(r[3]) : "r"(a));
}
__device__ __forceinline__ void ldmx4t(uint32_t* r, uint32_t a) {
    asm volatile("ldmatrix.sync.aligned.m8n8.x4.trans.shared.b16 {%0,%1,%2,%3}, [%4];"
                 : "=r"(r[0]), "=r"(r[1]), "=r"(r[2]), "=r"(r[3]) : "r"(a));
}
__device__ __forceinline__ void mma16816(float* d, const uint32_t* a, const uint32_t* b) {
    asm volatile("mma.sync.aligned.m16n8k16.row.col.f32.f16.f16.f32 "
                 "{%0,%1,%2,%3}, {%4,%5,%6,%7}, {%8,%9}, {%0,%1,%2,%3};"
                 : "+f"(d[0]), "+f"(d[1]), "+f"(d[2]), "+f"(d[3])
                 : "r"(a[0]), "r"(a[1]), "r"(a[2]), "r"(a[3]), "r"(b[0]), "r"(b[1]));
}
__device__ __forceinline__ void cpa16(uint32_t dst, const void* src) {
    asm volatile("cp.async.cg.shared.global [%0], [%1], 16;" :: "r"(dst), "l"(src));
}
__device__ __forceinline__ void cp_commit() { asm volatile("cp.async.commit_group;"); }
__device__ __forceinline__ void cp_wait1() { asm volatile("cp.async.wait_group 1;"); }
__device__ __forceinline__ void cp_wait0() { asm volatile("cp.async.wait_group 0;"); }

__device__ __forceinline__ uint32_t pack_h2(float f0, float f1) {
    __half2 h = __halves2half2(__float2half_rn(f0), __float2half_rn(f1));
    return *reinterpret_cast<uint32_t*>(&h);
}

__device__ __forceinline__ int expert_base(int e) {
    int b = 0;
#pragma unroll
    for (int i = 0; i < NE; i++)
        if (i < e) b += g_count[i];
    return b;
}

// SMEM layout (bytes). 2 stages. A: 128 rows x 144B. B: 64 k-rows x 272B.
#define A_STAGE 18432
#define B_STAGE 17408
#define SMO_A   1024
#define SMO_B   (1024 + 2 * A_STAGE)
#define SM_SZ   (SMO_B + 2 * B_STAGE)   // 72704 (x2 CTAs = 145408)

// ---------------- launch 1: weight fp16 convert + zero(counters) ------------
__global__ void conv_w_kernel(const float* __restrict__ W1,
                              const float* __restrict__ W2) {
    const int NW1 = NE * DIN * DHID / 16;    // 65536
    const int NW2 = NE * DHID * DOUT / 16;   // 65536
    int i = blockIdx.x * blockDim.x + threadIdx.x;
    if (i < NE) g_count[i] = 0;

    const float* src;
    __half* dst;
    size_t off;
    if (i < NW1) {
        src = W1; dst = g_W1h; off = (size_t)i * 16;
    } else {
        src = W2; dst = g_W2h; off = (size_t)(i - NW1) * 16;
    }
#pragma unroll
    for (int half = 0; half < 2; half++) {
        float4 a = *(const float4*)(src + off + half * 8);
        float4 b = *(const float4*)(src + off + half * 8 + 4);
        uint4 H;
        H.x = pack_h2(a.x, a.y);
        H.y = pack_h2(a.z, a.w);
        H.z = pack_h2(b.x, b.y);
        H.w = pack_h2(b.z, b.w);
        *(uint4*)(dst + off + half * 8) = H;
    }
}

// ---------------- launch 2: fused gate + x fp16 convert + zero(out) ---------
__global__ void gate_conv_x_kernel(const float* __restrict__ x,
                                   const float* __restrict__ Wg,
                                   float* __restrict__ out) {
    int gtid = blockIdx.x * blockDim.x + threadIdx.x;
    int gwarp = gtid >> 5;
    int lane = threadIdx.x & 31;
    if (gwarp >= BQ) return;

    float4 z = make_float4(0.f, 0.f, 0.f, 0.f);
    ((float4*)out)[gtid] = z;
    ((float4*)out)[gtid + BQ * DOUT / 8] = z;

    size_t off = (size_t)gwarp * DIN + lane * 8;
    float4 a = *(const float4*)(x + off);
    float4 b = *(const float4*)(x + off + 4);

    uint4 H;
    H.x = pack_h2(a.x, a.y);
    H.y = pack_h2(a.z, a.w);
    H.z = pack_h2(b.x, b.y);
    H.w = pack_h2(b.z, b.w);
    *(uint4*)(g_xh + off) = H;

    float v[8] = {a.x, a.y, a.z, a.w, b.x, b.y, b.z, b.w};
    float acc[NE];
#pragma unroll
    for (int e = 0; e < NE; e++) acc[e] = 0.f;
    const float* wr = Wg + (size_t)(lane * 8) * NE;
#pragma unroll
    for (int g = 0; g < 8; g++) {
        float4 w0 = __ldg((const float4*)(wr + g * NE));
        float4 w1 = __ldg((const float4*)(wr + g * NE + 4));
        acc[0] += v[g] * w0.x;  acc[1] += v[g] * w0.y;
        acc[2] += v[g] * w0.z;  acc[3] += v[g] * w0.w;
        acc[4] += v[g] * w1.x;  acc[5] += v[g] * w1.y;
        acc[6] += v[g] * w1.z;  acc[7] += v[g] * w1.w;
    }
#pragma unroll
    for (int e = 0; e < NE; e++)
#pragma unroll
        for (int o = 16; o > 0; o >>= 1)
            acc[e] += __shfl_xor_sync(0xffffffffu, acc[e], o);

    if (lane == 0) {
        int e0 = 0; float v0 = acc[0];
#pragma unroll
        for (int e = 1; e < NE; e++) if (acc[e] > v0) { v0 = acc[e]; e0 = e; }
        int e1 = (e0 == 0) ? 1 : 0; float v1 = acc[e1];
#pragma unroll
        for (int e = 0; e < NE; e++)
            if (e != e0 && acc[e] > v1) { v1 = acc[e]; e1 = e; }
        float x1 = expf(v1 - v0);
        float w0 = 1.0f / (1.0f + x1);
        int t = gwarp;
        int s0 = atomicAdd(&g_count[e0], 1);
        g_list[e0 * BQ + s0] = 2 * t;
        g_pw[2 * t] = w0;
        int s1 = atomicAdd(&g_count[e1], 1);
        g_list[e1 * BQ + s1] = 2 * t + 1;
        g_pw[2 * t + 1] = 1.0f - w0;
    }
}

// 4 MMAs per np group (2 mi x 2 j), single pass.
#define MMA_NP_GROUP(accv, ah, bh, np)                                           \
    do {                                                                         \
        const int j0 = 2 * (np), j1 = 2 * (np) + 1;                              \
        mma16816(accv[0][j0], ah[0], bh);                                        \
        mma16816(accv[0][j1], ah[0], bh + 2);                                    \
        mma16816(accv[1][j0], ah[1], bh);                                        \
        mma16816(accv[1][j1], ah[1], bh + 2);                                    \
    } while (0)

// ---------------- GEMM1 (persistent): H = relu(Xg @ W1[e] + b1[e]) ----------
__global__ void __launch_bounds__(256, 2)
gemm1_kernel(const float* __restrict__ b1) {
    extern __shared__ char smem[];
    uint32_t sbase = smem_u32(smem);
    int* tok = (int*)smem;
    const int tid = threadIdx.x;
    const int lane = tid & 31;
    const int wid = tid >> 5;
    const int wm = wid >> 1, wn = wid & 1;

    int base[NE + 1];
    base[0] = 0;
#pragma unroll
    for (int i = 0; i < NE; i++) base[i + 1] = base[i] + g_count[i];

    const int NTILES = 128 * 4 * NE;   // 4096
#pragma unroll 1
    for (int tix = blockIdx.x; tix < NTILES; tix += NPERS) {
        const int e  = tix >> 9;
        const int nt = (tix >> 7) & 3;
        const int mt = tix & 127;
        const int cnt = base[e + 1] - base[e];
        const int m0 = mt * 128;
        if (m0 >= cnt) continue;
        const int n0 = nt * 128;

        for (int r = tid; r < 128; r += 256) {
            int rr = m0 + r; if (rr >= cnt) rr = cnt - 1;
            tok[r] = g_list[e * BQ + rr] >> 1;
        }
        __syncthreads();

        auto issue = [&](int c, int s) {
            const int k0 = c * BKC;
            uint32_t abase = sbase + SMO_A + s * A_STAGE;
            uint32_t bbase = sbase + SMO_B + s * B_STAGE;
#pragma unroll
            for (int i = 0; i < 4; i++) {
                int idx = tid + i * 256;
                int row = idx >> 3, seg = idx & 7;
                const __half* src = g_xh + (size_t)tok[row] * DIN + k0 + seg * 8;
                cpa16(abase + row * 144 + seg * 16, src);
            }
#pragma unroll
            for (int i = 0; i < 4; i++) {
                int idx = tid + i * 256;
                int row = idx >> 4, seg = idx & 15;
                const __half* src =
                    g_W1h + ((size_t)e * DIN + k0 + row) * DHID + n0 + seg * 8;
                cpa16(bbase + row * 272 + seg * 16, src);
            }
            cp_commit();
        };

        float acc_s[2][8][4];
        float* acc[2][8];
#pragma unroll
        for (int a = 0; a < 2; a++)
#pragma unroll
            for (int b = 0; b < 8; b++) {
                acc[a][b] = acc_s[a][b];
#pragma unroll
                for (int q = 0; q < 4; q++) acc_s[a][b][q] = 0.f;
            }

        issue(0, 0);
        issue(1, 1);

        const int NC = DIN / BKC;   // 4
#pragma unroll 1
        for (int c = 0; c < NC; c++) {
            if (c == NC - 1) cp_wait0(); else cp_wait1();
            __syncthreads();
            int s = c & 1;
            uint32_t abase = sbase + SMO_A + s * A_STAGE;
            uint32_t bbase = sbase + SMO_B + s * B_STAGE;
#pragma unroll
            for (int ks = 0; ks < 4; ks++) {
                uint32_t ah[2][4];
#pragma unroll
                for (int mi = 0; mi < 2; mi++) {
                    uint32_t r = wm * 32 + mi * 16 + (lane & 15);
                    uint32_t co = ks * 32 + ((lane >> 4) << 4);
                    ldmx4(ah[mi], abase + r * 144 + co);
                }
#pragma unroll
                for (int np = 0; np < 4; np++) {
                    uint32_t kr = ks * 16 + ((lane >> 3) & 1) * 8 + (lane & 7);
                    uint32_t nc = (wn * 64 + np * 16 + ((lane >> 4) << 3)) * 2;
                    uint32_t bh[4];
                    ldmx4t(bh, bbase + kr * 272 + nc);
                    MMA_NP_GROUP(acc, ah, bh, np);
                }
            }
            __syncthreads();
            if (c + 2 < NC) issue(c + 2, s);
        }

        // epilogue: bias + relu + fp16 convert -> H (slot space)
        const int slot0 = base[e] + m0;
#pragma unroll
        for (int mi = 0; mi < 2; mi++) {
#pragma unroll
            for (int h = 0; h < 2; h++) {
                int rl = wm * 32 + mi * 16 + h * 8 + (lane >> 2);
                if (m0 + rl >= cnt) continue;
                size_t rowo = (size_t)(slot0 + rl) * DHID;
#pragma unroll
                for (int ni = 0; ni < 8; ni++) {
                    int gc = n0 + wn * 64 + ni * 8 + 2 * (lane & 3);
                    float f0 = fmaxf(acc_s[mi][ni][2 * h]     + __ldg(b1 + e * DHID + gc), 0.f);
                    float f1 = fmaxf(acc_s[mi][ni][2 * h + 1] + __ldg(b1 + e * DHID + gc + 1), 0.f);
                    *(uint32_t*)(g_Hh + rowo + gc) = pack_h2(f0, f1);
                }
            }
        }
        __syncthreads();
    }
}

// ---------------- GEMM2 (persistent) + fused combine -------------------------
__global__ void __launch_bounds__(256, 2)
gemm2_kernel(const float* __restrict__ b2, float* __restrict__ out) {
    extern __shared__ char smem[];
    uint32_t sbase = smem_u32(smem);
    const int tid = threadIdx.x;
    const int lane = tid & 31;
    const int wid = tid >> 5;
    const int wm = wid >> 1, wn = wid & 1;

    int base[NE + 1];
    base[0] = 0;
#pragma unroll
    for (int i = 0; i < NE; i++) base[i + 1] = base[i] + g_count[i];

    const int NTILES = 128 * 2 * NE;   // 2048
#pragma unroll 1
    for (int tix = blockIdx.x; tix < NTILES; tix += NPERS) {
        const int e  = tix >> 8;
        const int nt = (tix >> 7) & 1;
        const int mt = tix & 127;
        const int cnt = base[e + 1] - base[e];
        const int m0 = mt * 128;
        if (m0 >= cnt) continue;
        const int n0 = nt * 128;
        const int hbase = base[e];

        auto issue = [&](int c, int s) {
            const int k0 = c * BKC;
            uint32_t abase = sbase + SMO_A + s * A_STAGE;
            uint32_t bbase = sbase + SMO_B + s * B_STAGE;
#pragma unroll
            for (int i = 0; i < 4; i++) {
                int idx = tid + i * 256;
                int row = idx >> 3, seg = idx & 7;
                int rg = m0 + row; if (rg >= cnt) rg = cnt - 1;
                const __half* src =
                    g_Hh + (size_t)(hbase + rg) * DHID + k0 + seg * 8;
                cpa16(abase + row * 144 + seg * 16, src);
            }
#pragma unroll
            for (int i = 0; i < 4; i++) {
                int idx = tid + i * 256;
                int row = idx >> 4, seg = idx & 15;
                const __half* src =
                    g_W2h + ((size_t)e * DHID + k0 + row) * DOUT + n0 + seg * 8;
                cpa16(bbase + row * 272 + seg * 16, src);
            }
            cp_commit();
        };

        float acc_s[2][8][4];
        float* acc[2][8];
#pragma unroll
        for (int a = 0; a < 2; a++)
#pragma unroll
            for (int b = 0; b < 8; b++) {
                acc[a][b] = acc_s[a][b];
#pragma unroll
                for (int q = 0; q < 4; q++) acc_s[a][b][q] = 0.f;
            }

        issue(0, 0);
        issue(1, 1);

        const int NC = DHID / BKC;  // 8
#pragma unroll 1
        for (int c = 0; c < NC; c++) {
            if (c == NC - 1) cp_wait0(); else cp_wait1();
            __syncthreads();
            int s = c & 1;
            uint32_t abase = sbase + SMO_A + s * A_STAGE;
            uint32_t bbase = sbase + SMO_B + s * B_STAGE;
#pragma unroll
            for (int ks = 0; ks < 4; ks++) {
                uint32_t ah[2][4];
#pragma unroll
                for (int mi = 0; mi < 2; mi++) {
                    uint32_t r = wm * 32 + mi * 16 + (lane & 15);
                    uint32_t co = ks * 32 + ((lane >> 4) << 4);
                    ldmx4(ah[mi], abase + r * 144 + co);
                }
#pragma unroll
                for (int np = 0; np < 4; np++) {
                    uint32_t kr = ks * 16 + ((lane >> 3) & 1) * 8 + (lane & 7);
                    uint32_t nc = (wn * 64 + np * 16 + ((lane >> 4) << 3)) * 2;
                    uint32_t bh[4];
                    ldmx4t(bh, bbase + kr * 272 + nc);
                    MMA_NP_GROUP(acc, ah, bh, np);
                }
            }
            __syncthreads();
            if (c + 2 < NC) issue(c + 2, s);
        }

        // epilogue: +bias, scale by combine weight, accumulate into out[token]
#pragma unroll
        for (int mi = 0; mi < 2; mi++) {
#pragma unroll
            for (int h = 0; h < 2; h++) {
                int rl = wm * 32 + mi * 16 + h * 8 + (lane >> 2);
                if (m0 + rl >= cnt) continue;
                int pid = __ldg(&g_list[e * BQ + m0 + rl]);
                float w = g_pw[pid];
                float* orow = out + (size_t)(pid >> 1) * DOUT;
#pragma unroll
                for (int ni = 0; ni < 8; ni++) {
                    int gc = n0 + wn * 64 + ni * 8 + 2 * (lane & 3);
                    atomicAdd(orow + gc,
                              w * (acc_s[mi][ni][2 * h] + __ldg(b2 + e * DOUT + gc)));
                    atomicAdd(orow + gc + 1,
                              w * (acc_s[mi][ni][2 * h + 1] + __ldg(b2 + e * DOUT + gc + 1)));
                }
            }
        }
    }
}

// ---------------- launch -----------------------------------------------------
extern "C" void kernel_launch(void* const* d_in, const int* in_sizes, int n_in,
                              void* d_out, int out_size) {
    const float* x  = (const float*)d_in[0];
    const float* Wg = (const float*)d_in[1];
    const float* W1 = (const float*)d_in[2];
    const float* b1 = (const float*)d_in[3];
    const float* W2 = (const float*)d_in[4];
    const float* b2 = (const float*)d_in[5];
    float* out = (float*)d_out;

    cudaFuncSetAttribute(gemm1_kernel, cudaFuncAttributeMaxDynamicSharedMemorySize, SM_SZ);
    cudaFuncSetAttribute(gemm2_kernel, cudaFuncAttributeMaxDynamicSharedMemorySize, SM_SZ);

    const int NW = (NE * DIN * DHID + NE * DHID * DOUT) / 16;  // 131072

    // 4 launches; gemm2 is launch #4 (profiled slot)
    conv_w_kernel<<<NW / 256, 256>>>(W1, W2);
    gate_conv_x_kernel<<<BQ / 8, 256>>>(x, Wg, out);
    gemm1_kernel<<<NPERS, 256, SM_SZ>>>(b1);
    gemm2_kernel<<<NPERS, 256, SM_SZ>>>(b2, out);
}

// round 17
// speedup vs baseline: 1.0626x; 1.0626x over previous
#include <cuda_runtime.h>
#include <cuda_fp16.h>
#include <math.h>
#include <stdint.h>

#define BQ   16384
#define DIN  256
#define DHID 512
#define DOUT 256
#define NE   8
#define BKC  64
#define NPERS 296   // 2 CTAs/SM x 148 SMs; all co-resident (required for grid barrier)

// ---------------- scratch (static device globals; no allocations) ----------
__device__ int      g_count[NE];          // zero at entry (static init / reset by prev call)
__device__ unsigned g_barctr[2];          // monotonic grid-barrier counters
__device__ int      g_list[NE * BQ];      // pair id (2t+k) per (expert, slot)
__device__ float    g_pw[2 * BQ];
__device__ __align__(16) __half g_xh[(size_t)BQ * DIN];
__device__ __align__(16) __half g_W1h[NE * DIN * DHID];       // [e][k][n]
__device__ __align__(16) __half g_W2h[NE * DHID * DOUT];      // [e][k][n]
__device__ __align__(16) __half g_Hh[(size_t)2 * BQ * DHID];  // slot space

// ---------------- helpers ----------------------------------------------------
__device__ __forceinline__ uint32_t smem_u32(const void* p) {
    return (uint32_t)__cvta_generic_to_shared(p);
}
__device__ __forceinline__ void ldmx4(uint32_t* r, uint32_t a) {
    asm volatile("ldmatrix.sync.aligned.m8n8.x4.shared.b16 {%0,%1,%2,%3}, [%4];"
                 : "=r"(r[0]), "=r"(r[1]), "=r"(r[2]), "=r"(r[3]) : "r"(a));
}
__device__ __forceinline__ void ldmx4t(uint32_t* r, uint32_t a) {
    asm volatile("ldmatrix.sync.aligned.m8n8.x4.trans.shared.b16 {%0,%1,%2,%3}, [%4];"
                 : "=r"(r[0]), "=r"(r[1]), "=r"(r[2]), "=r"(r[3]) : "r"(a));
}
__device__ __forceinline__ void mma16816(float* d, const uint32_t* a, const uint32_t* b) {
    asm volatile("mma.sync.aligned.m16n8k16.row.col.f32.f16.f16.f32 "
                 "{%0,%1,%2,%3}, {%4,%5,%6,%7}, {%8,%9}, {%0,%1,%2,%3};"
                 : "+f"(d[0]), "+f"(d[1]), "+f"(d[2]), "+f"(d[3])
                 : "r"(a[0]), "r"(a[1]), "r"(a[2]), "r"(a[3]), "r"(b[0]), "r"(b[1]));
}
__device__ __forceinline__ void cpa16(uint32_t dst, const void* src) {
    asm volatile("cp.async.cg.shared.global [%0], [%1], 16;" :: "r"(dst), "l"(src));
}
__device__ __forceinline__ void cp_commit() { asm volatile("cp.async.commit_group;"); }
__device__ __forceinline__ void cp_wait1() { asm volatile("cp.async.wait_group 1;"); }
__device__ __forceinline__ void cp_wait0() { asm volatile("cp.async.wait_group 0;"); }

__device__ __forceinline__ uint32_t pack_h2(float f0, float f1) {
    __half2 h = __halves2half2(__float2half_rn(f0), __float2half_rn(f1));
    return *reinterpret_cast<uint32_t*>(&h);
}

// Monotonic all-CTA barrier (no reset needed; graph-replay safe).
__device__ __forceinline__ void grid_barrier(int idx) {
    __syncthreads();
    if (threadIdx.x == 0) {
        __threadfence();
        unsigned old = atomicAdd(&g_barctr[idx], 1u);
        unsigned target = (old / NPERS + 1u) * NPERS;
        while (atomicAdd(&g_barctr[idx], 0u) < target) __nanosleep(64);
        __threadfence();
    }
    __syncthreads();
}

// SMEM layout (bytes). tok: [0,512). prefix tables: [512, 656). stages from 1024.
// 2 stages. A: 128 rows x 144B. B: 64 k-rows x 272B.
#define A_STAGE 18432
#define B_STAGE 17408
#define SMO_A   1024
#define SMO_B   (1024 + 2 * A_STAGE)
#define SM_SZ   (SMO_B + 2 * B_STAGE)   // 72704 (x2 CTAs = 145408)

// prefix-table offsets (ints) within smem
#define SB_OFF   128   // sB[9]  : slot-space prefix
#define SP1_OFF  140   // sP1[9] : gemm1 tile prefix
#define SP2_OFF  152   // sP2[9] : gemm2 tile prefix

// 4 MMAs per np group (2 mi x 2 j), single pass.
#define MMA_NP_GROUP(accv, ah, bh, np)                                           \
    do {                                                                         \
        const int j0 = 2 * (np), j1 = 2 * (np) + 1;                              \
        mma16816(accv[0][j0], ah[0], bh);                                        \
        mma16816(accv[0][j1], ah[0], bh + 2);                                    \
        mma16816(accv[1][j0], ah[1], bh);                                        \
        mma16816(accv[1][j1], ah[1], bh + 2);                                    \
    } while (0)

// ---------------- the one persistent kernel ---------------------------------
__global__ void __launch_bounds__(256, 2)
moe_kernel(const float* __restrict__ x,   const float* __restrict__ Wg,
           const float* __restrict__ W1,  const float* __restrict__ b1,
           const float* __restrict__ W2,  const float* __restrict__ b2,
           float* __restrict__ out) {
    extern __shared__ char smem[];
    uint32_t sbase = smem_u32(smem);
    int* tok = (int*)smem;
    int* sI  = (int*)smem;        // prefix tables at int offsets SB/SP1/SP2
    const int tid = threadIdx.x;
    const int lane = tid & 31;
    const int wid = tid >> 5;
    const int wm = wid >> 1, wn = wid & 1;
    const int gtid = blockIdx.x * 256 + tid;

    // ================= phase A: weight convert + out zero + gate =============
    {
        // W1/W2 fp32 -> fp16 (8 elems per iter)
        const int NW1 = NE * DIN * DHID / 8;    // 131072
        const int NWT = NW1 + NE * DHID * DOUT / 8;
        for (int i = gtid; i < NWT; i += NPERS * 256) {
            const float* src; __half* dst; size_t off;
            if (i < NW1) { src = W1; dst = g_W1h; off = (size_t)i * 8; }
            else         { src = W2; dst = g_W2h; off = (size_t)(i - NW1) * 8; }
            float4 a = *(const float4*)(src + off);
            float4 b = *(const float4*)(src + off + 4);
            uint4 H;
            H.x = pack_h2(a.x, a.y); H.y = pack_h2(a.z, a.w);
            H.z = pack_h2(b.x, b.y); H.w = pack_h2(b.z, b.w);
            *(uint4*)(dst + off) = H;
        }
        // zero out
        float4 z = make_float4(0.f, 0.f, 0.f, 0.f);
        for (int i = gtid; i < BQ * DOUT / 4; i += NPERS * 256)
            ((float4*)out)[i] = z;
        // gate: one warp per token (grid-stride over warps)
        for (int t = blockIdx.x * 8 + wid; t < BQ; t += NPERS * 8) {
            size_t off = (size_t)t * DIN + lane * 8;
            float4 a = *(const float4*)(x + off);
            float4 b = *(const float4*)(x + off + 4);
            uint4 H;
            H.x = pack_h2(a.x, a.y); H.y = pack_h2(a.z, a.w);
            H.z = pack_h2(b.x, b.y); H.w = pack_h2(b.z, b.w);
            *(uint4*)(g_xh + off) = H;

            float v[8] = {a.x, a.y, a.z, a.w, b.x, b.y, b.z, b.w};
            float acc[NE];
#pragma unroll
            for (int e = 0; e < NE; e++) acc[e] = 0.f;
            const float* wr = Wg + (size_t)(lane * 8) * NE;
#pragma unroll
            for (int g = 0; g < 8; g++) {
                float4 w0 = __ldg((const float4*)(wr + g * NE));
                float4 w1 = __ldg((const float4*)(wr + g * NE + 4));
                acc[0] += v[g] * w0.x;  acc[1] += v[g] * w0.y;
                acc[2] += v[g] * w0.z;  acc[3] += v[g] * w0.w;
                acc[4] += v[g] * w1.x;  acc[5] += v[g] * w1.y;
                acc[6] += v[g] * w1.z;  acc[7] += v[g] * w1.w;
            }
#pragma unroll
            for (int e = 0; e < NE; e++)
#pragma unroll
                for (int o = 16; o > 0; o >>= 1)
                    acc[e] += __shfl_xor_sync(0xffffffffu, acc[e], o);
            if (lane == 0) {
                int e0 = 0; float v0 = acc[0];
#pragma unroll
                for (int e = 1; e < NE; e++) if (acc[e] > v0) { v0 = acc[e]; e0 = e; }
                int e1 = (e0 == 0) ? 1 : 0; float v1 = acc[e1];
#pragma unroll
                for (int e = 0; e < NE; e++)
                    if (e != e0 && acc[e] > v1) { v1 = acc[e]; e1 = e; }
                float x1 = expf(v1 - v0);
                float w0 = 1.0f / (1.0f + x1);
                int s0 = atomicAdd(&g_count[e0], 1);
                g_list[e0 * BQ + s0] = 2 * t;
                g_pw[2 * t] = w0;
                int s1 = atomicAdd(&g_count[e1], 1);
                g_list[e1 * BQ + s1] = 2 * t + 1;
                g_pw[2 * t + 1] = 1.0f - w0;
            }
        }
    }

    grid_barrier(0);

    // prefix tables (per-CTA smem copy)
    if (tid == 0) {
        int sb = 0, p1 = 0, p2 = 0;
        sI[SB_OFF] = 0; sI[SP1_OFF] = 0; sI[SP2_OFF] = 0;
#pragma unroll
        for (int e = 0; e < NE; e++) {
            int c = __ldcg(&g_count[e]);
            int mt = (c + 127) >> 7;
            sb += c; p1 += mt * 4; p2 += mt * 2;
            sI[SB_OFF + e + 1] = sb;
            sI[SP1_OFF + e + 1] = p1;
            sI[SP2_OFF + e + 1] = p2;
        }
    }
    __syncthreads();

    // ================= phase B: gemm1 (dense persistent tiles) ==============
    {
        const int T1 = sI[SP1_OFF + NE];
#pragma unroll 1
        for (int d = blockIdx.x; d < T1; d += NPERS) {
            int e = 0;
            while (d >= sI[SP1_OFF + e + 1]) e++;
            int r = d - sI[SP1_OFF + e];
            const int mt = r >> 2, nt = r & 3;
            const int cnt = sI[SB_OFF + e + 1] - sI[SB_OFF + e];
            const int m0 = mt * 128;
            const int n0 = nt * 128;
            const int slot0 = sI[SB_OFF + e] + m0;

            for (int rr = tid; rr < 128; rr += 256) {
                int q = m0 + rr; if (q >= cnt) q = cnt - 1;
                tok[rr] = __ldcg(&g_list[e * BQ + q]) >> 1;
            }
            __syncthreads();

            auto issue = [&](int c, int s) {
                const int k0 = c * BKC;
                uint32_t abase = sbase + SMO_A + s * A_STAGE;
                uint32_t bbase = sbase + SMO_B + s * B_STAGE;
#pragma unroll
                for (int i = 0; i < 4; i++) {
                    int idx = tid + i * 256;
                    int row = idx >> 3, seg = idx & 7;
                    const __half* src = g_xh + (size_t)tok[row] * DIN + k0 + seg * 8;
                    cpa16(abase + row * 144 + seg * 16, src);
                }
#pragma unroll
                for (int i = 0; i < 4; i++) {
                    int idx = tid + i * 256;
                    int row = idx >> 4, seg = idx & 15;
                    const __half* src =
                        g_W1h + ((size_t)e * DIN + k0 + row) * DHID + n0 + seg * 8;
                    cpa16(bbase + row * 272 + seg * 16, src);
                }
                cp_commit();
            };

            float acc_s[2][8][4];
            float* acc[2][8];
#pragma unroll
            for (int a = 0; a < 2; a++)
#pragma unroll
                for (int b = 0; b < 8; b++) {
                    acc[a][b] = acc_s[a][b];
#pragma unroll
                    for (int q = 0; q < 4; q++) acc_s[a][b][q] = 0.f;
                }

            issue(0, 0);
            issue(1, 1);

            const int NC = DIN / BKC;   // 4
#pragma unroll 1
            for (int c = 0; c < NC; c++) {
                if (c == NC - 1) cp_wait0(); else cp_wait1();
                __syncthreads();
                int s = c & 1;
                uint32_t abase = sbase + SMO_A + s * A_STAGE;
                uint32_t bbase = sbase + SMO_B + s * B_STAGE;
#pragma unroll
                for (int ks = 0; ks < 4; ks++) {
                    uint32_t ah[2][4];
#pragma unroll
                    for (int mi = 0; mi < 2; mi++) {
                        uint32_t rr = wm * 32 + mi * 16 + (lane & 15);
                        uint32_t co = ks * 32 + ((lane >> 4) << 4);
                        ldmx4(ah[mi], abase + rr * 144 + co);
                    }
#pragma unroll
                    for (int np = 0; np < 4; np++) {
                        uint32_t kr = ks * 16 + ((lane >> 3) & 1) * 8 + (lane & 7);
                        uint32_t nc = (wn * 64 + np * 16 + ((lane >> 4) << 3)) * 2;
                        uint32_t bh[4];
                        ldmx4t(bh, bbase + kr * 272 + nc);
                        MMA_NP_GROUP(acc, ah, bh, np);
                    }
                }
                __syncthreads();
                if (c + 2 < NC) issue(c + 2, s);
            }

            // epilogue: bias + relu + fp16 -> H (slot space)
#pragma unroll
            for (int mi = 0; mi < 2; mi++) {
#pragma unroll
                for (int h = 0; h < 2; h++) {
                    int rl = wm * 32 + mi * 16 + h * 8 + (lane >> 2);
                    if (m0 + rl >= cnt) continue;
                    size_t rowo = (size_t)(slot0 + rl) * DHID;
#pragma unroll
                    for (int ni = 0; ni < 8; ni++) {
                        int gc = n0 + wn * 64 + ni * 8 + 2 * (lane & 3);
                        float f0 = fmaxf(acc_s[mi][ni][2 * h]     + __ldg(b1 + e * DHID + gc), 0.f);
                        float f1 = fmaxf(acc_s[mi][ni][2 * h + 1] + __ldg(b1 + e * DHID + gc + 1), 0.f);
                        *(uint32_t*)(g_Hh + rowo + gc) = pack_h2(f0, f1);
                    }
                }
            }
            __syncthreads();
        }
    }

    grid_barrier(1);

    // reset counters for next call (all reads of g_count happened before barrier 1)
    if (blockIdx.x == 0 && tid < NE) g_count[tid] = 0;

    // ================= phase C: gemm2 + fused combine ========================
    {
        const int T2 = sI[SP2_OFF + NE];
#pragma unroll 1
        for (int d = blockIdx.x; d < T2; d += NPERS) {
            int e = 0;
            while (d >= sI[SP2_OFF + e + 1]) e++;
            int r = d - sI[SP2_OFF + e];
            const int mt = r >> 1, nt = r & 1;
            const int cnt = sI[SB_OFF + e + 1] - sI[SB_OFF + e];
            const int m0 = mt * 128;
            const int n0 = nt * 128;
            const int hbase = sI[SB_OFF + e];

            auto issue = [&](int c, int s) {
                const int k0 = c * BKC;
                uint32_t abase = sbase + SMO_A + s * A_STAGE;
                uint32_t bbase = sbase + SMO_B + s * B_STAGE;
#pragma unroll
                for (int i = 0; i < 4; i++) {
                    int idx = tid + i * 256;
                    int row = idx >> 3, seg = idx & 7;
                    int rg = m0 + row; if (rg >= cnt) rg = cnt - 1;
                    const __half* src =
                        g_Hh + (size_t)(hbase + rg) * DHID + k0 + seg * 8;
                    cpa16(abase + row * 144 + seg * 16, src);
                }
#pragma unroll
                for (int i = 0; i < 4; i++) {
                    int idx = tid + i * 256;
                    int row = idx >> 4, seg = idx & 15;
                    const __half* src =
                        g_W2h + ((size_t)e * DHID + k0 + row) * DOUT + n0 + seg * 8;
                    cpa16(bbase + row * 272 + seg * 16, src);
                }
                cp_commit();
            };

            float acc_s[2][8][4];
            float* acc[2][8];
#pragma unroll
            for (int a = 0; a < 2; a++)
#pragma unroll
                for (int b = 0; b < 8; b++) {
                    acc[a][b] = acc_s[a][b];
#pragma unroll
                    for (int q = 0; q < 4; q++) acc_s[a][b][q] = 0.f;
                }

            issue(0, 0);
            issue(1, 1);

            const int NC = DHID / BKC;  // 8
#pragma unroll 1
            for (int c = 0; c < NC; c++) {
                if (c == NC - 1) cp_wait0(); else cp_wait1();
                __syncthreads();
                int s = c & 1;
                uint32_t abase = sbase + SMO_A + s * A_STAGE;
                uint32_t bbase = sbase + SMO_B + s * B_STAGE;
#pragma unroll
                for (int ks = 0; ks < 4; ks++) {
                    uint32_t ah[2][4];
#pragma unroll
                    for (int mi = 0; mi < 2; mi++) {
                        uint32_t rr = wm * 32 + mi * 16 + (lane & 15);
                        uint32_t co = ks * 32 + ((lane >> 4) << 4);
                        ldmx4(ah[mi], abase + rr * 144 + co);
                    }
#pragma unroll
                    for (int np = 0; np < 4; np++) {
                        uint32_t kr = ks * 16 + ((lane >> 3) & 1) * 8 + (lane & 7);
                        uint32_t nc = (wn * 64 + np * 16 + ((lane >> 4) << 3)) * 2;
                        uint32_t bh[4];
                        ldmx4t(bh, bbase + kr * 272 + nc);
                        MMA_NP_GROUP(acc, ah, bh, np);
                    }
                }
                __syncthreads();
                if (c + 2 < NC) issue(c + 2, s);
            }

            // epilogue: +bias, scale by combine weight, atomically add to out
#pragma unroll
            for (int mi = 0; mi < 2; mi++) {
#pragma unroll
                for (int h = 0; h < 2; h++) {
                    int rl = wm * 32 + mi * 16 + h * 8 + (lane >> 2);
                    if (m0 + rl >= cnt) continue;
                    int pid = __ldcg(&g_list[e * BQ + m0 + rl]);
                    float w = __ldcg(&g_pw[pid]);
                    float* orow = out + (size_t)(pid >> 1) * DOUT;
#pragma unroll
                    for (int ni = 0; ni < 8; ni++) {
                        int gc = n0 + wn * 64 + ni * 8 + 2 * (lane & 3);
                        atomicAdd(orow + gc,
                                  w * (acc_s[mi][ni][2 * h] + __ldg(b2 + e * DOUT + gc)));
                        atomicAdd(orow + gc + 1,
                                  w * (acc_s[mi][ni][2 * h + 1] + __ldg(b2 + e * DOUT + gc + 1)));
                    }
                }
            }
            __syncthreads();
        }
    }
}

// ---------------- launch -----------------------------------------------------
extern "C" void kernel_launch(void* const* d_in, const int* in_sizes, int n_in,
                              void* d_out, int out_size) {
    const float* x  = (const float*)d_in[0];
    const float* Wg = (const float*)d_in[1];
    const float* W1 = (const float*)d_in[2];
    const float* b1 = (const float*)d_in[3];
    const float* W2 = (const float*)d_in[4];
    const float* b2 = (const float*)d_in[5];
    float* out = (float*)d_out;

    cudaFuncSetAttribute(moe_kernel, cudaFuncAttributeMaxDynamicSharedMemorySize, SM_SZ);
    moe_kernel<<<NPERS, 256, SM_SZ>>>(x, Wg, W1, b1, W2, b2, out);
}